// round 2
// baseline (speedup 1.0000x reference)
#include <cuda_runtime.h>
#include <cstdint>

// Problem dims (fixed by reference setup_inputs)
#define BATCH 1024
#define TSTEPS 200
#define DDIM 128

// Tiling
#define NBLK 128          // 32 row-tiles x 4 col-tiles, 1 block/SM
#define BM 32             // rows per block
#define BN 32             // cells (h-columns) per block
#define ASTR 34           // padded row stride (floats) for sA: 8B aligned, low-conflict
#define SB_FLOATS (256*128)
#define SA_FLOATS (256*ASTR)
#define SMEM_BYTES ((SB_FLOATS + SA_FLOATS)*4)

// Persistent state (scratch) in device globals (no allocation allowed)
__device__ float g_h1[2][BATCH*DDIM];
__device__ float g_h2[2][BATCH*DDIM];
__device__ unsigned g_bar_count;
__device__ unsigned g_bar_gen;

__device__ __forceinline__ unsigned long long pack2(float v){
    unsigned long long r;
    asm("mov.b64 %0, {%1, %1};" : "=l"(r) : "f"(v));
    return r;
}
__device__ __forceinline__ void fma2(unsigned long long &acc, unsigned long long a, unsigned long long b){
    asm("fma.rn.f32x2 %0, %1, %2, %0;" : "+l"(acc) : "l"(a), "l"(b));
}
__device__ __forceinline__ float2 unpack2(unsigned long long v){
    float2 f;
    asm("mov.b64 {%0, %1}, %2;" : "=f"(f.x), "=f"(f.y) : "l"(v));
    return f;
}
__device__ __forceinline__ float fsig(float x){
    return __fdividef(1.f, 1.f + __expf(-x));
}
__device__ __forceinline__ float ftanh_(float x){
    x = fminf(15.f, fmaxf(-15.f, x));
    float e = __expf(2.f * x);
    return __fdividef(e - 1.f, e + 1.f);
}

// Grid-wide barrier: generation-counting, safe across graph replays
// (count returns to 0 after each barrier; gen monotonically increases).
__device__ __forceinline__ void grid_barrier(){
    __syncthreads();
    if (threadIdx.x == 0){
        __threadfence();                                  // release my writes to L2
        unsigned my = *(volatile unsigned*)&g_bar_gen;    // read gen BEFORE arriving
        unsigned old = atomicAdd(&g_bar_count, 1);
        if (old == NBLK - 1){
            g_bar_count = 0;
            __threadfence();
            atomicAdd(&g_bar_gen, 1);
        } else {
            while (*(volatile unsigned*)&g_bar_gen == my) { }
        }
        __threadfence();
    }
    __syncthreads();
}

// 32x128x256 GEMM tile: acc[rowpair][gate] are f32x2 over (row, row+1)
__device__ __forceinline__ void tile_gemm(const float* __restrict__ sA,
                                          const float* __restrict__ sB,
                                          unsigned long long acc[2][4],
                                          int ty, int tx){
    const float* ap = sA + 4*ty;      // rows 4ty..4ty+3, pairs (0,1) and (2,3)
    const float* bp = sB + 4*tx;      // 4 gates of cell tx (interleaved layout)
    #pragma unroll 8
    for (int k = 0; k < 256; ++k){
        unsigned long long a0 = *(const unsigned long long*)(ap + k*ASTR);
        unsigned long long a1 = *(const unsigned long long*)(ap + k*ASTR + 2);
        float4 bv = *(const float4*)(bp + k*128);
        unsigned long long b0 = pack2(bv.x);
        unsigned long long b1 = pack2(bv.y);
        unsigned long long b2 = pack2(bv.z);
        unsigned long long b3 = pack2(bv.w);
        fma2(acc[0][0], a0, b0); fma2(acc[0][1], a0, b1);
        fma2(acc[0][2], a0, b2); fma2(acc[0][3], a0, b3);
        fma2(acc[1][0], a1, b0); fma2(acc[1][1], a1, b1);
        fma2(acc[1][2], a1, b2); fma2(acc[1][3], a1, b3);
    }
}

extern __shared__ float smem[];

__global__ void __launch_bounds__(256, 1)
lstm_persistent_kernel(const float* __restrict__ x,
                       const float* __restrict__ W,
                       const float* __restrict__ U,
                       const float* __restrict__ bias,
                       float* __restrict__ out)
{
    float* sB = smem;               // [256][128] combined [W;U] slice, gate-interleaved
    float* sA = smem + SB_FLOATS;   // [256][ASTR] transposed A tile

    const int tid = threadIdx.x;
    const int tx = tid & 31;        // cell within tile
    const int ty = tid >> 5;        // row group (0..7), rows 4ty..4ty+3
    const int colt = blockIdx.x & 3;
    const int rowt = blockIdx.x >> 2;
    const int n0 = colt * BN;
    const int r0 = rowt * BM;

    // ---- Load combined weights [W;U] into SMEM once. Column order j = n*4 + g.
    for (int idx = tid; idx < 256*128; idx += 256){
        int k = idx >> 7;           // 0..255
        int j = idx & 127;
        int n = j >> 2, g = j & 3;
        int c = g*128 + n0 + n;     // column in the 4D gate layout (i,f,g,o)
        float v = (k < 128) ? W[k*512 + c] : U[(k-128)*512 + c];
        sB[k*128 + j] = v;
    }

    // ---- Per-thread bias (packed for f32x2 accumulators)
    unsigned long long bias2[4];
    #pragma unroll
    for (int g = 0; g < 4; ++g) bias2[g] = pack2(bias[g*128 + n0 + tx]);

    // ---- Zero initial state (buffers persist across graph replays)
    float c1[4] = {0.f,0.f,0.f,0.f};
    float c2[4] = {0.f,0.f,0.f,0.f};
    #pragma unroll
    for (int j = 0; j < 4; ++j){
        int rg = r0 + 4*ty + j;
        g_h1[0][rg*DDIM + n0 + tx] = 0.f;
        g_h2[0][rg*DDIM + n0 + tx] = 0.f;
    }
    grid_barrier();   // also covers the sB fill via its __syncthreads

    float h1n[4];
    unsigned long long acc[2][4];

    for (int t = 0; t < TSTEPS; ++t){
        const int p  = t & 1;
        const int pn = p ^ 1;

        // ===== Layer 1: A = [x_t | h1(t)] (transposed into sA[k][r]) =====
        {
            const int k = tid;
            #pragma unroll 4
            for (int i = 0; i < 32; ++i){
                int rg = r0 + i;
                float v = (k < 128) ? x[(rg*TSTEPS + t)*DDIM + k]
                                    : __ldcg(&g_h1[p][rg*DDIM + (k - 128)]);
                sA[k*ASTR + i] = v;
            }
        }
        __syncthreads();
        #pragma unroll
        for (int g = 0; g < 4; ++g){ acc[0][g] = bias2[g]; acc[1][g] = bias2[g]; }
        tile_gemm(sA, sB, acc, ty, tx);
        __syncthreads();   // sA reuse guard for layer-2 fill

        #pragma unroll
        for (int rp = 0; rp < 2; ++rp){
            float2 zi = unpack2(acc[rp][0]);
            float2 zf = unpack2(acc[rp][1]);
            float2 zg = unpack2(acc[rp][2]);
            float2 zo = unpack2(acc[rp][3]);
            {
                int j = rp*2;
                float cn = fsig(zf.x)*c1[j] + fsig(zi.x)*ftanh_(zg.x);
                c1[j] = cn;  h1n[j] = fsig(zo.x)*ftanh_(cn);
            }
            {
                int j = rp*2 + 1;
                float cn = fsig(zf.y)*c1[j] + fsig(zi.y)*ftanh_(zg.y);
                c1[j] = cn;  h1n[j] = fsig(zo.y)*ftanh_(cn);
            }
        }
        #pragma unroll
        for (int j = 0; j < 4; ++j){
            int rg = r0 + 4*ty + j;
            g_h1[pn][rg*DDIM + n0 + tx] = h1n[j];
        }

        grid_barrier();   // h1(t+1) fully written, globally visible

        // ===== Layer 2: A = [h1n | h2(t)] =====
        {
            const int k = tid;
            #pragma unroll 4
            for (int i = 0; i < 32; ++i){
                int rg = r0 + i;
                float v = (k < 128) ? __ldcg(&g_h1[pn][rg*DDIM + k])
                                    : __ldcg(&g_h2[p][rg*DDIM + (k - 128)]);
                sA[k*ASTR + i] = v;
            }
        }
        __syncthreads();
        #pragma unroll
        for (int g = 0; g < 4; ++g){ acc[0][g] = bias2[g]; acc[1][g] = bias2[g]; }
        tile_gemm(sA, sB, acc, ty, tx);
        __syncthreads();

        #pragma unroll
        for (int rp = 0; rp < 2; ++rp){
            float2 zi = unpack2(acc[rp][0]);
            float2 zf = unpack2(acc[rp][1]);
            float2 zg = unpack2(acc[rp][2]);
            float2 zo = unpack2(acc[rp][3]);
            {
                int j = rp*2;
                float cn = fsig(zf.x)*c2[j] + fsig(zi.x)*ftanh_(zg.x);
                c2[j] = cn;
                float hv = fsig(zo.x)*ftanh_(cn) + h1n[j];      // residual
                int rg = r0 + 4*ty + j;
                g_h2[pn][rg*DDIM + n0 + tx] = hv;
                out[(rg*TSTEPS + t)*DDIM + n0 + tx] = hv;
            }
            {
                int j = rp*2 + 1;
                float cn = fsig(zf.y)*c2[j] + fsig(zi.y)*ftanh_(zg.y);
                c2[j] = cn;
                float hv = fsig(zo.y)*ftanh_(cn) + h1n[j];
                int rg = r0 + 4*ty + j;
                g_h2[pn][rg*DDIM + n0 + tx] = hv;
                out[(rg*TSTEPS + t)*DDIM + n0 + tx] = hv;
            }
        }
        // No barrier here: next iteration's layer-1 inputs (g_h1[pn]) were
        // already published at the barrier above; g_h2[pn] readers are
        // separated by the next iteration's barrier.
    }
}

extern "C" void kernel_launch(void* const* d_in, const int* in_sizes, int n_in,
                              void* d_out, int out_size)
{
    const float* x    = (const float*)d_in[0];
    const float* W    = (const float*)d_in[1];
    const float* U    = (const float*)d_in[2];
    const float* bias = (const float*)d_in[3];
    // d_in[4] = seq_len, intentionally unused (reference ignores it)
    float* out = (float*)d_out;

    cudaFuncSetAttribute(lstm_persistent_kernel,
                         cudaFuncAttributeMaxDynamicSharedMemorySize, SMEM_BYTES);
    lstm_persistent_kernel<<<NBLK, 256, SMEM_BYTES>>>(x, W, U, bias, out);
}